// round 1
// baseline (speedup 1.0000x reference)
#include <cuda_runtime.h>
#include <float.h>
#include <stdint.h>

// ---------------------------------------------------------------------------
// MVCNN: pooled = raggedmax_v(concat(x^T, x_art^T))  -> 3-layer MLP
//   x      [64, 2048, 256] f32
//   x_art  [64, 2048, 256] f32
//   lens   [64] i32
//   w1 [4096,4096] b1[4096]  w2 [4096,4096] b2[4096]  w3 [4096,1000] b3[1000]
//   out [64, 1000] f32
// ---------------------------------------------------------------------------

#define BATCH 64
#define DIM   4096
#define VIEWS 256
#define OUTN  1000

// scratch (device globals; no allocation allowed)
__device__ float g_pooled[BATCH * DIM];
__device__ float g_h1[BATCH * DIM];
__device__ float g_h2[BATCH * DIM];
__device__ float g_part[4][BATCH * 1024];   // split-K partials for gemm3 (ldc=1024)

// ---------------------------------------------------------------------------
// Ragged max-pool: one warp per (b, d) row, coalesced along v.
// ---------------------------------------------------------------------------
__global__ void pool_kernel(const float* __restrict__ x,
                            const float* __restrict__ xa,
                            const int*   __restrict__ lens,
                            float* __restrict__ out)
{
    int warp = (blockIdx.x * blockDim.x + threadIdx.x) >> 5;
    int lane = threadIdx.x & 31;
    if (warp >= BATCH * DIM) return;
    int b = warp >> 12;          // /4096
    int d = warp & 4095;

    const float* src = (d < 2048)
        ? (x  + ((size_t)(b * 2048 + d)       ) * VIEWS)
        : (xa + ((size_t)(b * 2048 + (d-2048))) * VIEWS);

    int len = lens[b];
    if (len < 1) len = 1;
    if (len > VIEWS) len = VIEWS;

    float m = -FLT_MAX;
    for (int v = lane; v < len; v += 32)
        m = fmaxf(m, src[v]);

    #pragma unroll
    for (int o = 16; o; o >>= 1)
        m = fmaxf(m, __shfl_xor_sync(0xffffffffu, m, o));

    if (lane == 0) out[warp] = m;
}

// ---------------------------------------------------------------------------
// Tiled fp32 GEMM:  C[64, N] = act( A[64,4096] @ W[4096,N] + bias )
// BM=32 BN=64 BK=16, 256 threads, thread tile 2x4, register prefetch.
// SPLITK: grid.z splits K into kChunk ranges, writes partials (no bias/act).
// ---------------------------------------------------------------------------
template<bool RELU, bool BIAS, bool SPLITK>
__global__ __launch_bounds__(256)
void gemm_kernel(const float* __restrict__ A,
                 const float* __restrict__ W,
                 const float* __restrict__ bias,
                 float* __restrict__ C,
                 int N, int ldc, int kChunk)
{
    constexpr int BM = 32, BN = 64, BK = 16, K = DIM;
    __shared__ float As[BK][BM + 2];   // +2 pad: bank spread + float2 alignment
    __shared__ float Ws[BK][BN];

    const int tid = threadIdx.x;
    const int n0  = blockIdx.x * BN;
    const int m0  = blockIdx.y * BM;
    const int kb  = SPLITK ? blockIdx.z * kChunk : 0;
    if (SPLITK) C += (size_t)blockIdx.z * BATCH * 1024;

    const int rg = tid >> 4;            // 0..15 -> rows m0 + 2*rg + {0,1}
    const int cg = tid & 15;            // 0..15 -> cols n0 + 4*cg + {0..3}
    const int tA_m = tid >> 3;          // 0..31
    const int tA_k = (tid & 7) << 1;    // 0,2,..,14
    const int tW_k = tid >> 4;          // 0..15
    const int tW_n = (tid & 15) << 2;   // 0,4,..,60

    const float* Aptr = A + (size_t)(m0 + tA_m) * K + kb + tA_k;
    const float* Wptr = W + (size_t)(kb + tW_k) * N + n0 + tW_n;
    const bool wFull = (n0 + BN <= N);

    float2 pa;
    float4 pw;

    auto loadA = [&](int t) {
        pa = *reinterpret_cast<const float2*>(Aptr + t * BK);
    };
    auto loadW = [&](int t) {
        const float* p = Wptr + (size_t)t * BK * N;
        if (wFull) {
            pw = *reinterpret_cast<const float4*>(p);
        } else {
            int nbase = n0 + tW_n;
            pw.x = (nbase + 0 < N) ? p[0] : 0.f;
            pw.y = (nbase + 1 < N) ? p[1] : 0.f;
            pw.z = (nbase + 2 < N) ? p[2] : 0.f;
            pw.w = (nbase + 3 < N) ? p[3] : 0.f;
        }
    };
    auto commit = [&]() {
        As[tA_k    ][tA_m] = pa.x;
        As[tA_k + 1][tA_m] = pa.y;
        *reinterpret_cast<float4*>(&Ws[tW_k][tW_n]) = pw;
    };

    float acc[2][4];
    #pragma unroll
    for (int i = 0; i < 2; ++i)
        #pragma unroll
        for (int j = 0; j < 4; ++j) acc[i][j] = 0.f;

    const int nkt = kChunk / BK;

    loadA(0); loadW(0);
    commit();
    __syncthreads();

    for (int t = 1; t < nkt; ++t) {
        loadA(t); loadW(t);              // prefetch next tile into registers
        #pragma unroll
        for (int k = 0; k < BK; ++k) {
            float2 a = *reinterpret_cast<const float2*>(&As[k][rg * 2]);
            float4 w = *reinterpret_cast<const float4*>(&Ws[k][cg * 4]);
            acc[0][0] = fmaf(a.x, w.x, acc[0][0]);
            acc[0][1] = fmaf(a.x, w.y, acc[0][1]);
            acc[0][2] = fmaf(a.x, w.z, acc[0][2]);
            acc[0][3] = fmaf(a.x, w.w, acc[0][3]);
            acc[1][0] = fmaf(a.y, w.x, acc[1][0]);
            acc[1][1] = fmaf(a.y, w.y, acc[1][1]);
            acc[1][2] = fmaf(a.y, w.z, acc[1][2]);
            acc[1][3] = fmaf(a.y, w.w, acc[1][3]);
        }
        __syncthreads();
        commit();
        __syncthreads();
    }
    // last tile
    #pragma unroll
    for (int k = 0; k < BK; ++k) {
        float2 a = *reinterpret_cast<const float2*>(&As[k][rg * 2]);
        float4 w = *reinterpret_cast<const float4*>(&Ws[k][cg * 4]);
        acc[0][0] = fmaf(a.x, w.x, acc[0][0]);
        acc[0][1] = fmaf(a.x, w.y, acc[0][1]);
        acc[0][2] = fmaf(a.x, w.z, acc[0][2]);
        acc[0][3] = fmaf(a.x, w.w, acc[0][3]);
        acc[1][0] = fmaf(a.y, w.x, acc[1][0]);
        acc[1][1] = fmaf(a.y, w.y, acc[1][1]);
        acc[1][2] = fmaf(a.y, w.z, acc[1][2]);
        acc[1][3] = fmaf(a.y, w.w, acc[1][3]);
    }

    #pragma unroll
    for (int i = 0; i < 2; ++i) {
        int m = m0 + rg * 2 + i;
        #pragma unroll
        for (int j = 0; j < 4; ++j) {
            int n = n0 + cg * 4 + j;
            if (n < N) {
                float v = acc[i][j];
                if (BIAS) v += bias[n];
                if (RELU) v = fmaxf(v, 0.f);
                C[(size_t)m * ldc + n] = v;
            }
        }
    }
}

// ---------------------------------------------------------------------------
// Split-K reduction for final layer: out = sum(partials) + b3
// ---------------------------------------------------------------------------
__global__ void reduce_kernel(const float* __restrict__ b3,
                              float* __restrict__ out)
{
    int idx = blockIdx.x * blockDim.x + threadIdx.x;
    if (idx >= BATCH * OUTN) return;
    int m = idx / OUTN;
    int n = idx - m * OUTN;
    float s = b3[n];
    #pragma unroll
    for (int z = 0; z < 4; ++z)
        s += g_part[z][m * 1024 + n];
    out[idx] = s;
}

// ---------------------------------------------------------------------------
// launch
// ---------------------------------------------------------------------------
extern "C" void kernel_launch(void* const* d_in, const int* in_sizes, int n_in,
                              void* d_out, int out_size)
{
    const float* x    = (const float*)d_in[0];
    const float* xa   = (const float*)d_in[1];
    const int*   lens = (const int*)  d_in[2];
    const float* w1   = (const float*)d_in[3];
    const float* b1   = (const float*)d_in[4];
    const float* w2   = (const float*)d_in[5];
    const float* b2   = (const float*)d_in[6];
    const float* w3   = (const float*)d_in[7];
    const float* b3   = (const float*)d_in[8];
    float* out = (float*)d_out;

    float *pooled, *h1, *h2;
    cudaGetSymbolAddress((void**)&pooled, g_pooled);
    cudaGetSymbolAddress((void**)&h1, g_h1);
    cudaGetSymbolAddress((void**)&h2, g_h2);
    float* part0;
    cudaGetSymbolAddress((void**)&part0, g_part);

    // 1) ragged max pool: one warp per row, 262144 rows
    {
        int warps = BATCH * DIM;
        int threads = 256;
        int blocks = (warps * 32 + threads - 1) / threads;
        pool_kernel<<<blocks, threads>>>(x, xa, lens, pooled);
    }

    // 2) h1 = relu(pooled @ w1 + b1)   [64,4096]
    {
        dim3 grid(DIM / 64, BATCH / 32, 1);
        gemm_kernel<true, true, false><<<grid, 256>>>(pooled, w1, b1, h1,
                                                      DIM, DIM, DIM);
    }

    // 3) h2 = relu(h1 @ w2 + b2)       [64,4096]
    {
        dim3 grid(DIM / 64, BATCH / 32, 1);
        gemm_kernel<true, true, false><<<grid, 256>>>(h1, w2, b2, h2,
                                                      DIM, DIM, DIM);
    }

    // 4) out = h2 @ w3 + b3            [64,1000], split-K x4 + reduce
    {
        dim3 grid((OUTN + 63) / 64, BATCH / 32, 4);
        gemm_kernel<false, false, true><<<grid, 256>>>(h2, w3, nullptr, part0,
                                                       OUTN, 1024, DIM / 4);
        int total = BATCH * OUTN;
        reduce_kernel<<<(total + 255) / 256, 256>>>(b3, out);
    }
}

// round 3
// speedup vs baseline: 3.1036x; 3.1036x over previous
#include <cuda_runtime.h>
#include <cuda_bf16.h>
#include <float.h>
#include <stdint.h>

// ---------------------------------------------------------------------------
// MVCNN: ragged max-pool -> 3-layer MLP.
// GEMMs via mma.sync.m16n8k16 (bf16 hi/lo split, f32 acc) — portable sm_80+
// ISA (harness ptxas targets sm_103 base; tcgen05 requires sm_103a -> unusable).
//   C[64, N] = act[64, 4096] @ W[4096, N]
//   act pre-split into bf16 hi/lo by pool/reduce epilogues.
//   W converted fp32 -> bf16 hi/lo in-kernel.
//   3 MMAs per step: Ah*Wh + Al*Wh + Ah*Wl  (err ~2^-16)
// ---------------------------------------------------------------------------

#define BATCH 64
#define DIM   4096
#define VIEWS 256
#define OUTN  1000

__device__ __align__(256) __nv_bfloat16 g_actH[BATCH * DIM];
__device__ __align__(256) __nv_bfloat16 g_actL[BATCH * DIM];
__device__ __align__(256) float g_part[8][DIM * BATCH];   // [ksplit][feat][batch]

// ---------------------------------------------------------------------------
// helpers
// ---------------------------------------------------------------------------
__device__ __forceinline__ uint32_t smem_u32(const void* p) {
    uint32_t a;
    asm("{ .reg .u64 t; cvta.to.shared.u64 t, %1; cvt.u32.u64 %0, t; }"
        : "=r"(a) : "l"(p));
    return a;
}
__device__ __forceinline__ void cp16(uint32_t dst, const void* src) {
    asm volatile("cp.async.cg.shared.global [%0], [%1], 16;"
                 :: "r"(dst), "l"(src));
}
__device__ __forceinline__ void cp_commit() {
    asm volatile("cp.async.commit_group;" ::: "memory");
}
template<int N> __device__ __forceinline__ void cp_wait() {
    asm volatile("cp.async.wait_group %0;" :: "n"(N) : "memory");
}
__device__ __forceinline__ void ldsm4(uint32_t* r, uint32_t a) {
    asm volatile("ldmatrix.sync.aligned.m8n8.x4.shared.b16 {%0,%1,%2,%3}, [%4];"
        : "=r"(r[0]), "=r"(r[1]), "=r"(r[2]), "=r"(r[3]) : "r"(a));
}
__device__ __forceinline__ void ldsm4t(uint32_t* r, uint32_t a) {
    asm volatile("ldmatrix.sync.aligned.m8n8.x4.trans.shared.b16 {%0,%1,%2,%3}, [%4];"
        : "=r"(r[0]), "=r"(r[1]), "=r"(r[2]), "=r"(r[3]) : "r"(a));
}
__device__ __forceinline__ void mma16816(float* c, const uint32_t* a,
                                         uint32_t b0, uint32_t b1) {
    asm volatile(
        "mma.sync.aligned.m16n8k16.row.col.f32.bf16.bf16.f32 "
        "{%0,%1,%2,%3}, {%4,%5,%6,%7}, {%8,%9}, {%0,%1,%2,%3};"
        : "+f"(c[0]), "+f"(c[1]), "+f"(c[2]), "+f"(c[3])
        : "r"(a[0]), "r"(a[1]), "r"(a[2]), "r"(a[3]), "r"(b0), "r"(b1));
}

// ---------------------------------------------------------------------------
// Ragged max-pool -> bf16 hi/lo activations  act[batch][feat]
// ---------------------------------------------------------------------------
__global__ void pool_kernel(const float* __restrict__ x,
                            const float* __restrict__ xa,
                            const int*   __restrict__ lens,
                            __nv_bfloat16* __restrict__ actH,
                            __nv_bfloat16* __restrict__ actL)
{
    int warp = (blockIdx.x * blockDim.x + threadIdx.x) >> 5;
    int lane = threadIdx.x & 31;
    if (warp >= BATCH * DIM) return;
    int b = warp >> 12;
    int d = warp & 4095;

    const float* src = (d < 2048)
        ? (x  + ((size_t)(b * 2048 + d)        ) * VIEWS)
        : (xa + ((size_t)(b * 2048 + (d - 2048))) * VIEWS);

    int len = lens[b];
    len = max(1, min(len, VIEWS));

    float m = -FLT_MAX;
    for (int v0 = lane * 4; v0 < len; v0 += 128) {
        float4 v = *reinterpret_cast<const float4*>(src + v0);
        m = fmaxf(m, v.x);
        if (v0 + 1 < len) m = fmaxf(m, v.y);
        if (v0 + 2 < len) m = fmaxf(m, v.z);
        if (v0 + 3 < len) m = fmaxf(m, v.w);
    }
    #pragma unroll
    for (int o = 16; o; o >>= 1)
        m = fmaxf(m, __shfl_xor_sync(0xffffffffu, m, o));

    if (lane == 0) {
        __nv_bfloat16 h = __float2bfloat16(m);
        actH[warp] = h;
        actL[warp] = __float2bfloat16(m - __bfloat162float(h));
    }
}

// ---------------------------------------------------------------------------
// GEMM: part[ks][feat][batch] = act[64, kchunk] @ W[kchunk, Ntile]
//   grid (N/64, KSPLIT), 128 threads (4 warps; warp = 16-col n slice)
//   smem: 2 stages x { WH 8K | WL 8K | AH 8K | AL 8K } (XOR-swizzled)
// ---------------------------------------------------------------------------
#define STAGE  32768
#define OFF_WH 0
#define OFF_WL 8192
#define OFF_AH 16384
#define OFF_AL 24576
#define GEMM_SMEM (2 * STAGE + 1024)

__global__ void __launch_bounds__(128) gemm_mma(
    const float* __restrict__ W, int N,
    const __nv_bfloat16* __restrict__ actH,
    const __nv_bfloat16* __restrict__ actL,
    float* __restrict__ partBase, int kchunk)
{
    extern __shared__ char smraw[];
    const uint32_t s0 = (smem_u32(smraw) + 1023) & ~1023u;
    const int tid = threadIdx.x;
    const int warp = tid >> 5, lane = tid & 31;
    const int n0 = blockIdx.x * 64;
    const int kb = blockIdx.y * kchunk;
    float* part = partBase + (size_t)blockIdx.y * (DIM * BATCH);
    const int nst = kchunk >> 6;

    // W fp32 load mapping: thread -> (k row, 32-col half); 8 x float4 per stage
    const int wk = tid >> 1;
    const int wn = (tid & 1) * 32;
    const float* wgp = W + (size_t)(kb + wk) * N + n0 + wn;
    const uint32_t wswz = (uint32_t)(wk & 7) << 4;
    const uint32_t wsrow = s0 + (uint32_t)wk * 128;

    // A cp.async mapping: thread -> (m row, 32-k half); 4 x 16B per tile
    const int am = tid >> 1;
    const int ak = (tid & 1) * 32;
    const __nv_bfloat16* agpH = actH + (size_t)am * DIM + kb + ak;
    const __nv_bfloat16* agpL = actL + (size_t)am * DIM + kb + ak;
    uint32_t aoffc[4];
    #pragma unroll
    for (int c = 0; c < 4; ++c)
        aoffc[c] = (uint32_t)am * 128 + ((uint32_t)((ak + c * 8) * 2) ^ ((uint32_t)(am & 7) << 4));

    // ldmatrix A (row-major [m][k]): lane -> row within m16, k-half
    const uint32_t arow = (lane & 7) + ((lane >> 3) & 1) * 8;
    const uint32_t ak2  = ((lane >> 4) & 1) * 16;        // k-half byte offset
    const uint32_t aswz = (uint32_t)(lane & 7) << 4;
    const uint32_t aoff = arow * 128;

    // ldmatrix B trans (W smem [k][n]): lane -> k row, n-half per warp slice
    const uint32_t brow = (lane & 7) + ((lane >> 3) & 1) * 8;
    const uint32_t bn2  = (uint32_t)((warp * 16 + ((lane >> 4) & 1) * 8) * 2)
                        ^ ((uint32_t)(lane & 7) << 4);
    const uint32_t boff = brow * 128 + bn2;

    float acc[4][2][4];
    #pragma unroll
    for (int i = 0; i < 4; ++i)
        #pragma unroll
        for (int j = 0; j < 2; ++j)
            #pragma unroll
            for (int q = 0; q < 4; ++q) acc[i][j][q] = 0.f;

    float4 wreg[8];

    auto loadW = [&](int s) {
        const float* p = wgp + (size_t)s * 64 * N;
        #pragma unroll
        for (int j = 0; j < 8; ++j) {
            int col = n0 + wn + j * 4;
            if (col + 3 < N) {
                wreg[j] = *reinterpret_cast<const float4*>(p + j * 4);
            } else {
                float4 v;
                v.x = (col + 0 < N) ? p[j * 4 + 0] : 0.f;
                v.y = (col + 1 < N) ? p[j * 4 + 1] : 0.f;
                v.z = (col + 2 < N) ? p[j * 4 + 2] : 0.f;
                v.w = (col + 3 < N) ? p[j * 4 + 3] : 0.f;
                wreg[j] = v;
            }
        }
    };
    auto storeW = [&](int buf) {
        const uint32_t base = wsrow + buf * STAGE;
        #pragma unroll
        for (int j = 0; j < 8; ++j) {
            uint32_t off = ((uint32_t)((wn + j * 4) * 2)) ^ wswz;
            float4 f = wreg[j];
            uint32_t h01, h23, l01, l23;
            asm("cvt.rn.satfinite.bf16x2.f32 %0, %1, %2;" : "=r"(h01) : "f"(f.y), "f"(f.x));
            asm("cvt.rn.satfinite.bf16x2.f32 %0, %1, %2;" : "=r"(h23) : "f"(f.w), "f"(f.z));
            float l0 = f.x - __uint_as_float(h01 << 16);
            float l1 = f.y - __uint_as_float(h01 & 0xffff0000u);
            float l2 = f.z - __uint_as_float(h23 << 16);
            float l3 = f.w - __uint_as_float(h23 & 0xffff0000u);
            asm("cvt.rn.satfinite.bf16x2.f32 %0, %1, %2;" : "=r"(l01) : "f"(l1), "f"(l0));
            asm("cvt.rn.satfinite.bf16x2.f32 %0, %1, %2;" : "=r"(l23) : "f"(l3), "f"(l2));
            asm volatile("st.shared.v2.b32 [%0], {%1,%2};"
                         :: "r"(base + OFF_WH + off), "r"(h01), "r"(h23));
            asm volatile("st.shared.v2.b32 [%0], {%1,%2};"
                         :: "r"(base + OFF_WL + off), "r"(l01), "r"(l23));
        }
    };
    auto issueA = [&](int s, int buf) {
        const uint32_t base = s0 + buf * STAGE;
        #pragma unroll
        for (int c = 0; c < 4; ++c) {
            cp16(base + OFF_AH + aoffc[c], agpH + s * 64 + c * 8);
            cp16(base + OFF_AL + aoffc[c], agpL + s * 64 + c * 8);
        }
        cp_commit();
    };
    auto compute = [&](int buf) {
        const uint32_t base = s0 + buf * STAGE;
        #pragma unroll
        for (int ks = 0; ks < 4; ++ks) {
            uint32_t bh[4], bl[4];
            ldsm4t(bh, base + OFF_WH + ks * 2048 + boff);
            ldsm4t(bl, base + OFF_WL + ks * 2048 + boff);
            const uint32_t kx = (uint32_t)(ks * 32 + ak2) ^ aswz;
            #pragma unroll
            for (int mt = 0; mt < 4; ++mt) {
                uint32_t ah[4], al[4];
                ldsm4(ah, base + OFF_AH + mt * 2048 + aoff + kx);
                ldsm4(al, base + OFF_AL + mt * 2048 + aoff + kx);
                mma16816(acc[mt][0], ah, bh[0], bh[1]);
                mma16816(acc[mt][1], ah, bh[2], bh[3]);
                mma16816(acc[mt][0], al, bh[0], bh[1]);
                mma16816(acc[mt][1], al, bh[2], bh[3]);
                mma16816(acc[mt][0], ah, bl[0], bl[1]);
                mma16816(acc[mt][1], ah, bl[2], bl[3]);
            }
        }
    };

    issueA(0, 0);
    loadW(0);
    for (int s = 0; s < nst; ++s) {
        const int buf = s & 1;
        storeW(buf);
        if (s + 1 < nst) {
            issueA(s + 1, buf ^ 1);
            loadW(s + 1);
            cp_wait<1>();
        } else {
            cp_wait<0>();
        }
        __syncthreads();
        compute(buf);
        __syncthreads();
    }

    // epilogue: scatter f32 partials  part[feat*64 + batch]
    const int g = lane >> 2, tg = lane & 3;
    #pragma unroll
    for (int mt = 0; mt < 4; ++mt)
        #pragma unroll
        for (int nt = 0; nt < 2; ++nt) {
            int feat = n0 + warp * 16 + nt * 8 + tg * 2;
            int bat  = mt * 16 + g;
            float* p = part + (size_t)feat * 64 + bat;
            p[0]      = acc[mt][nt][0];
            p[64]     = acc[mt][nt][1];
            p[8]      = acc[mt][nt][2];
            p[64 + 8] = acc[mt][nt][3];
        }
}

// ---------------------------------------------------------------------------
// Reduce K-splits + bias + relu -> next-layer bf16 hi/lo activations
// ---------------------------------------------------------------------------
__global__ void reduce_bias_relu(const float* __restrict__ bias,
                                 __nv_bfloat16* __restrict__ actH,
                                 __nv_bfloat16* __restrict__ actL)
{
    int idx = blockIdx.x * 256 + threadIdx.x;   // 64*4096
    int n = idx >> 12;       // batch
    int m = idx & 4095;      // feat
    float s = bias[m];
    #pragma unroll
    for (int z = 0; z < 4; ++z) s += g_part[z][m * 64 + n];
    s = fmaxf(s, 0.f);
    __nv_bfloat16 h = __float2bfloat16(s);
    actH[idx] = h;
    actL[idx] = __float2bfloat16(s - __bfloat162float(h));
}

__global__ void reduce_out(const float* __restrict__ b3,
                           float* __restrict__ out)
{
    int idx = blockIdx.x * 256 + threadIdx.x;
    if (idx >= BATCH * OUTN) return;
    int n = idx / OUTN;      // batch
    int m = idx - n * OUTN;  // feat
    float s = b3[m];
    #pragma unroll
    for (int z = 0; z < 8; ++z) s += g_part[z][m * 64 + n];
    out[idx] = s;
}

// ---------------------------------------------------------------------------
// launch
// ---------------------------------------------------------------------------
extern "C" void kernel_launch(void* const* d_in, const int* in_sizes, int n_in,
                              void* d_out, int out_size)
{
    const float* x    = (const float*)d_in[0];
    const float* xa   = (const float*)d_in[1];
    const int*   lens = (const int*)  d_in[2];
    const float* w1   = (const float*)d_in[3];
    const float* b1   = (const float*)d_in[4];
    const float* w2   = (const float*)d_in[5];
    const float* b2   = (const float*)d_in[6];
    const float* w3   = (const float*)d_in[7];
    const float* b3   = (const float*)d_in[8];
    float* out = (float*)d_out;

    __nv_bfloat16 *actH, *actL;
    float* part;
    cudaGetSymbolAddress((void**)&actH, g_actH);
    cudaGetSymbolAddress((void**)&actL, g_actL);
    cudaGetSymbolAddress((void**)&part, g_part);

    cudaFuncSetAttribute(gemm_mma, cudaFuncAttributeMaxDynamicSharedMemorySize,
                         GEMM_SMEM);

    // 1) pool -> act hi/lo
    {
        int warps = BATCH * DIM;
        int blocks = (warps * 32 + 255) / 256;
        pool_kernel<<<blocks, 256>>>(x, xa, lens, actH, actL);
    }
    // 2) layer 1: ksplit 4, kchunk 1024
    gemm_mma<<<dim3(64, 4), 128, GEMM_SMEM>>>(w1, DIM, actH, actL, part, 1024);
    reduce_bias_relu<<<1024, 256>>>(b1, actH, actL);
    // 3) layer 2
    gemm_mma<<<dim3(64, 4), 128, GEMM_SMEM>>>(w2, DIM, actH, actL, part, 1024);
    reduce_bias_relu<<<1024, 256>>>(b2, actH, actL);
    // 4) layer 3: N=1000, ksplit 8, kchunk 512
    gemm_mma<<<dim3(16, 8), 128, GEMM_SMEM>>>(w3, OUTN, actH, actL, part, 512);
    reduce_out<<<(BATCH * OUTN + 255) / 256, 256>>>(b3, out);
}